// round 5
// baseline (speedup 1.0000x reference)
#include <cuda_runtime.h>
#include <cuda_fp16.h>
#include <cstdint>

#define DEV static __device__ __forceinline__

namespace {
constexpr int Mdim = 8192;   // B*S
constexpr int Ndim = 4096;   // out features
constexpr int Kdim = 4096;   // in features
constexpr int BM = 128, BN = 256, BK = 64;
constexpr int STAGES = 4;
constexpr int KTILES = Kdim / BK;                          // 64
constexpr int A_STAGE_BYTES = BM * BK * 2;                 // 16384 (128B rows)
constexpr int B_STAGE_BYTES = BN * BK * 2;                 // 32768
constexpr int STAGE_BYTES = A_STAGE_BYTES + B_STAGE_BYTES; // 49152
constexpr int DYN_SMEM = STAGES * STAGE_BYTES + 256;       // + alignment pad
}

// fp16 operand buffers (static device globals: allocation-free scratch)
__device__ __align__(1024) __half g_A[(size_t)Mdim * Kdim];  // x as fp16, [m][k]
__device__ __align__(1024) __half g_B[(size_t)Ndim * Kdim];  // W^T as fp16, [n][k]

// ---------------- PTX helpers (base-ISA only: sm_80/75 features) ----------------

DEV uint32_t smem_u32(const void* p) {
    uint32_t a;
    asm("{ .reg .u64 t; cvta.to.shared.u64 t, %1; cvt.u32.u64 %0, t; }"
        : "=r"(a) : "l"(p));
    return a;
}

DEV void cpasync16(uint32_t dst, const void* src) {
    asm volatile("cp.async.cg.shared.global [%0], [%1], 16;\n"
                 :: "r"(dst), "l"(src));
}

#define CP_COMMIT() asm volatile("cp.async.commit_group;" ::: "memory")
#define CP_WAIT(N)  asm volatile("cp.async.wait_group %0;" :: "n"(N) : "memory")

DEV void ldsm_x4(uint32_t& r0, uint32_t& r1, uint32_t& r2, uint32_t& r3,
                 uint32_t addr) {
    asm volatile("ldmatrix.sync.aligned.m8n8.x4.shared.b16 {%0,%1,%2,%3}, [%4];"
                 : "=r"(r0), "=r"(r1), "=r"(r2), "=r"(r3) : "r"(addr));
}

DEV void mma16816(float* d, const uint32_t* a, uint32_t b0, uint32_t b1) {
    asm volatile(
        "mma.sync.aligned.m16n8k16.row.col.f32.f16.f16.f32 "
        "{%0,%1,%2,%3}, {%4,%5,%6,%7}, {%8,%9}, {%0,%1,%2,%3};"
        : "+f"(d[0]), "+f"(d[1]), "+f"(d[2]), "+f"(d[3])
        : "r"(a[0]), "r"(a[1]), "r"(a[2]), "r"(a[3]), "r"(b0), "r"(b1));
}

// ---------------- converters ----------------

__global__ void conv_x_kernel(const float* __restrict__ x) {
    size_t i = ((size_t)blockIdx.x * blockDim.x + threadIdx.x) * 4;
    float4 v = *reinterpret_cast<const float4*>(x + i);
    union { __half2 h[2]; uint2 u; } cv;
    cv.h[0] = __floats2half2_rn(v.x, v.y);
    cv.h[1] = __floats2half2_rn(v.z, v.w);
    *reinterpret_cast<uint2*>(g_A + i) = cv.u;
}

// W[k][n] (row-major) -> g_B[n][k] fp16 (K-major), 32x32 smem tile transpose
__global__ void conv_w_kernel(const float* __restrict__ W) {
    __shared__ float t[32][33];
    int n0 = blockIdx.x * 32, k0 = blockIdx.y * 32;
    int tx = threadIdx.x, ty = threadIdx.y;  // block (32, 8)
#pragma unroll
    for (int j = 0; j < 32; j += 8)
        t[ty + j][tx] = W[(size_t)(k0 + ty + j) * Ndim + n0 + tx];
    __syncthreads();
#pragma unroll
    for (int j = 0; j < 32; j += 8)
        g_B[(size_t)(n0 + ty + j) * Kdim + k0 + tx] = __float2half_rn(t[tx][ty + j]);
}

// ---------------- GEMM (cp.async + ldmatrix + mma.sync HMMA) ----------------

// 128B rows (64 halves = BK), 16B chunks XOR-swizzled: chunk' = chunk ^ (row&7)
DEV void load_stage(uint32_t ubase, int stage, int kt, int m0, int n0) {
    const int tid = threadIdx.x;
    const uint32_t sA = ubase + stage * STAGE_BYTES;
    const uint32_t sB = sA + A_STAGE_BYTES;
    const size_t k0 = (size_t)kt * BK;
    // A tile: 128 rows x 8 chunks = 1024 chunks / 256 thr = 4 each
#pragma unroll
    for (int i = 0; i < (BM * 8) / 256; i++) {
        int idx = tid + i * 256;
        int r = idx >> 3, c = idx & 7;
        const char* src = (const char*)(g_A + (size_t)(m0 + r) * Kdim + k0) + c * 16;
        cpasync16(sA + r * 128 + ((c ^ (r & 7)) << 4), src);
    }
    // B tile: 256 rows x 8 chunks = 2048 chunks / 256 thr = 8 each
#pragma unroll
    for (int i = 0; i < (BN * 8) / 256; i++) {
        int idx = tid + i * 256;
        int r = idx >> 3, c = idx & 7;
        const char* src = (const char*)(g_B + (size_t)(n0 + r) * Kdim + k0) + c * 16;
        cpasync16(sB + r * 128 + ((c ^ (r & 7)) << 4), src);
    }
    CP_COMMIT();
}

__global__ void __launch_bounds__(256, 1)
gemm_kernel(const float* __restrict__ bias, float* __restrict__ out) {
    extern __shared__ char dynsmem[];
    const uint32_t raw = smem_u32(dynsmem);
    const uint32_t ubase = (raw + 127u) & ~127u;

    const int tid = threadIdx.x;
    const int wid = tid >> 5;
    const int lane = tid & 31;
    const int m0 = blockIdx.y * BM;
    const int n0 = blockIdx.x * BN;
    const int wm = (wid >> 2) * 64;   // warp grid: 2 (m) x 4 (n)
    const int wn = (wid & 3) * 64;

    float acc[4][8][4];
#pragma unroll
    for (int mi = 0; mi < 4; mi++)
#pragma unroll
        for (int nj = 0; nj < 8; nj++)
#pragma unroll
            for (int r = 0; r < 4; r++) acc[mi][nj][r] = 0.0f;

    // prologue: fill stages 0..2
#pragma unroll
    for (int kt = 0; kt < STAGES - 1; kt++) load_stage(ubase, kt, kt, m0, n0);

    // ldmatrix lane addressing (stage-relative)
    // A frag (x4): lanes 0-15 rows m0-15 chunk lo; lanes 16-31 same rows chunk hi
    const int a_row = wm + (lane & 15);
    const int a_chi = lane >> 4;  // 0/1 -> +16B (k+8)
    // B frag (x4): lanes 0-7 n0-7 lo; 8-15 n0-7 hi; 16-23 n8-15 lo; 24-31 n8-15 hi
    const int b_row = wn + ((lane >> 4) << 3) + (lane & 7);
    const int b_chi = (lane >> 3) & 1;

    // double-buffered fragments
    uint32_t a[2][4][4], b[2][4][4];

    auto load_frags = [&](uint32_t sA, uint32_t sB, int ks, int buf) {
#pragma unroll
        for (int mi = 0; mi < 4; mi++) {
            int row = a_row + mi * 16;
            int ch = ks * 2 + a_chi;
            ldsm_x4(a[buf][mi][0], a[buf][mi][1], a[buf][mi][2], a[buf][mi][3],
                    sA + row * 128 + ((ch ^ (row & 7)) << 4));
        }
#pragma unroll
        for (int j = 0; j < 4; j++) {
            int row = b_row + j * 16;
            int ch = ks * 2 + b_chi;
            ldsm_x4(b[buf][j][0], b[buf][j][1], b[buf][j][2], b[buf][j][3],
                    sB + row * 128 + ((ch ^ (row & 7)) << 4));
        }
    };

    for (int kt = 0; kt < KTILES; kt++) {
        CP_WAIT(2);
        __syncthreads();

        const uint32_t sA = ubase + (kt % STAGES) * STAGE_BYTES;
        const uint32_t sB = sA + A_STAGE_BYTES;

        // prefetch frags for ks=0 first, then issue the stage refill so the
        // cp.async issue burst overlaps the ldmatrix latency + mma work.
        load_frags(sA, sB, 0, 0);

        {   // refill the stage consumed this iter with tile kt+3
            const int lt = kt + STAGES - 1;
            if (lt < KTILES) load_stage(ubase, lt % STAGES, lt, m0, n0);
            else CP_COMMIT();  // keep wait_group accounting uniform
        }

#pragma unroll
        for (int ks = 0; ks < BK / 16; ks++) {
            const int cur = ks & 1;
            if (ks < BK / 16 - 1) load_frags(sA, sB, ks + 1, cur ^ 1);
#pragma unroll
            for (int mi = 0; mi < 4; mi++)
#pragma unroll
                for (int j = 0; j < 4; j++) {
                    mma16816(acc[mi][2 * j],     a[cur][mi], b[cur][j][0], b[cur][j][1]);
                    mma16816(acc[mi][2 * j + 1], a[cur][mi], b[cur][j][2], b[cur][j][3]);
                }
        }
    }

    // Epilogue: direct gmem float2 stores, bias fused.
    // D frag: d0,d1 -> (row = lane>>2, col = 2*(lane&3)); d2,d3 -> row+8.
    const int er = lane >> 2;
    const int ec = (lane & 3) * 2;
#pragma unroll
    for (int mi = 0; mi < 4; mi++) {
        const size_t row = (size_t)(m0 + wm + mi * 16 + er);
#pragma unroll
        for (int nj = 0; nj < 8; nj++) {
            const int col = n0 + wn + nj * 8 + ec;
            const float2 bv = __ldg(reinterpret_cast<const float2*>(bias + col));
            float2 v0, v1;
            v0.x = acc[mi][nj][0] + bv.x;
            v0.y = acc[mi][nj][1] + bv.y;
            v1.x = acc[mi][nj][2] + bv.x;
            v1.y = acc[mi][nj][3] + bv.y;
            *reinterpret_cast<float2*>(out + row * Ndim + col) = v0;
            *reinterpret_cast<float2*>(out + (row + 8) * Ndim + col) = v1;
        }
    }
}

// ---------------- launch ----------------

extern "C" void kernel_launch(void* const* d_in, const int* in_sizes, int n_in,
                              void* d_out, int out_size) {
    const float* x = nullptr;
    const float* W = nullptr;
    const float* bias = nullptr;
    for (int i = 0; i < n_in; i++) {
        if (in_sizes[i] == Mdim * Kdim) x = (const float*)d_in[i];
        else if (in_sizes[i] == Kdim * Ndim) W = (const float*)d_in[i];
        else if (in_sizes[i] == Ndim) bias = (const float*)d_in[i];
    }
    float* out = (float*)d_out;

    cudaFuncSetAttribute(gemm_kernel,
                         cudaFuncAttributeMaxDynamicSharedMemorySize, DYN_SMEM);

    // x -> fp16 (K-major)
    conv_x_kernel<<<(int)((size_t)Mdim * Kdim / 4 / 256), 256>>>(x);
    // W -> W^T fp16 (K-major)
    conv_w_kernel<<<dim3(Ndim / 32, Kdim / 32), dim3(32, 8)>>>(W);
    // GEMM
    gemm_kernel<<<dim3(Ndim / BN, Mdim / BM), 256, DYN_SMEM>>>(bias, out);
}

// round 10
// speedup vs baseline: 1.0278x; 1.0278x over previous
#include <cuda_runtime.h>
#include <cuda_fp16.h>
#include <cstdint>

#define DEV static __device__ __forceinline__

namespace {
constexpr int Mdim = 8192;   // B*S
constexpr int Ndim = 4096;   // out features
constexpr int Kdim = 4096;   // in features
constexpr int BM = 128, BN = 256, BK = 64;
constexpr int NTHREADS = 512;                              // 16 warps, 4/SMSP
constexpr int STAGES = 4;
constexpr int KTILES = Kdim / BK;                          // 64
constexpr int A_STAGE_BYTES = BM * BK * 2;                 // 16384 (128B rows)
constexpr int B_STAGE_BYTES = BN * BK * 2;                 // 32768
constexpr int STAGE_BYTES = A_STAGE_BYTES + B_STAGE_BYTES; // 49152
constexpr int DYN_SMEM = STAGES * STAGE_BYTES + 256;       // + alignment pad
}

// fp16 operand buffers (static device globals: allocation-free scratch)
__device__ __align__(1024) __half g_A[(size_t)Mdim * Kdim];  // x as fp16, [m][k]
__device__ __align__(1024) __half g_B[(size_t)Ndim * Kdim];  // W^T as fp16, [n][k]

// ---------------- PTX helpers (base-ISA only: sm_80/75 features) ----------------

DEV uint32_t smem_u32(const void* p) {
    uint32_t a;
    asm("{ .reg .u64 t; cvta.to.shared.u64 t, %1; cvt.u32.u64 %0, t; }"
        : "=r"(a) : "l"(p));
    return a;
}

DEV void cpasync16(uint32_t dst, const void* src) {
    asm volatile("cp.async.cg.shared.global [%0], [%1], 16;\n"
                 :: "r"(dst), "l"(src));
}

#define CP_COMMIT() asm volatile("cp.async.commit_group;" ::: "memory")
#define CP_WAIT(N)  asm volatile("cp.async.wait_group %0;" :: "n"(N) : "memory")

DEV void ldsm_x4(uint32_t& r0, uint32_t& r1, uint32_t& r2, uint32_t& r3,
                 uint32_t addr) {
    asm volatile("ldmatrix.sync.aligned.m8n8.x4.shared.b16 {%0,%1,%2,%3}, [%4];"
                 : "=r"(r0), "=r"(r1), "=r"(r2), "=r"(r3) : "r"(addr));
}

DEV void mma16816(float* d, const uint32_t* a, uint32_t b0, uint32_t b1) {
    asm volatile(
        "mma.sync.aligned.m16n8k16.row.col.f32.f16.f16.f32 "
        "{%0,%1,%2,%3}, {%4,%5,%6,%7}, {%8,%9}, {%0,%1,%2,%3};"
        : "+f"(d[0]), "+f"(d[1]), "+f"(d[2]), "+f"(d[3])
        : "r"(a[0]), "r"(a[1]), "r"(a[2]), "r"(a[3]), "r"(b0), "r"(b1));
}

// ---------------- converters ----------------

__global__ void conv_x_kernel(const float* __restrict__ x) {
    size_t i = ((size_t)blockIdx.x * blockDim.x + threadIdx.x) * 4;
    float4 v = *reinterpret_cast<const float4*>(x + i);
    union { __half2 h[2]; uint2 u; } cv;
    cv.h[0] = __floats2half2_rn(v.x, v.y);
    cv.h[1] = __floats2half2_rn(v.z, v.w);
    *reinterpret_cast<uint2*>(g_A + i) = cv.u;
}

// W[k][n] (row-major) -> g_B[n][k] fp16 (K-major), 32x32 smem tile transpose
__global__ void conv_w_kernel(const float* __restrict__ W) {
    __shared__ float t[32][33];
    int n0 = blockIdx.x * 32, k0 = blockIdx.y * 32;
    int tx = threadIdx.x, ty = threadIdx.y;  // block (32, 8)
#pragma unroll
    for (int j = 0; j < 32; j += 8)
        t[ty + j][tx] = W[(size_t)(k0 + ty + j) * Ndim + n0 + tx];
    __syncthreads();
#pragma unroll
    for (int j = 0; j < 32; j += 8)
        g_B[(size_t)(n0 + ty + j) * Kdim + k0 + tx] = __float2half_rn(t[tx][ty + j]);
}

// ---------------- GEMM (cp.async + ldmatrix + mma.sync HMMA) ----------------

// 128B rows (64 halves = BK), 16B chunks XOR-swizzled: chunk' = chunk ^ (row&7)
DEV void load_stage(uint32_t ubase, int stage, int kt, int m0, int n0) {
    const int tid = threadIdx.x;
    const uint32_t sA = ubase + stage * STAGE_BYTES;
    const uint32_t sB = sA + A_STAGE_BYTES;
    const size_t k0 = (size_t)kt * BK;
    // A tile: 128 rows x 8 chunks = 1024 chunks / 512 thr = 2 each
#pragma unroll
    for (int i = 0; i < (BM * 8) / NTHREADS; i++) {
        int idx = tid + i * NTHREADS;
        int r = idx >> 3, c = idx & 7;
        const char* src = (const char*)(g_A + (size_t)(m0 + r) * Kdim + k0) + c * 16;
        cpasync16(sA + r * 128 + ((c ^ (r & 7)) << 4), src);
    }
    // B tile: 256 rows x 8 chunks = 2048 chunks / 512 thr = 4 each
#pragma unroll
    for (int i = 0; i < (BN * 8) / NTHREADS; i++) {
        int idx = tid + i * NTHREADS;
        int r = idx >> 3, c = idx & 7;
        const char* src = (const char*)(g_B + (size_t)(n0 + r) * Kdim + k0) + c * 16;
        cpasync16(sB + r * 128 + ((c ^ (r & 7)) << 4), src);
    }
    CP_COMMIT();
}

__global__ void __launch_bounds__(NTHREADS, 1)
gemm_kernel(const float* __restrict__ bias, float* __restrict__ out) {
    extern __shared__ char dynsmem[];
    const uint32_t raw = smem_u32(dynsmem);
    const uint32_t ubase = (raw + 127u) & ~127u;

    const int tid = threadIdx.x;
    const int wid = tid >> 5;
    const int lane = tid & 31;
    const int m0 = blockIdx.y * BM;
    const int n0 = blockIdx.x * BN;
    const int wm = (wid & 1) * 64;    // warp grid: 2 (m) x 8 (n), tile 64x32
    const int wn = (wid >> 1) * 32;

    float acc[4][4][4];
#pragma unroll
    for (int mi = 0; mi < 4; mi++)
#pragma unroll
        for (int nj = 0; nj < 4; nj++)
#pragma unroll
            for (int r = 0; r < 4; r++) acc[mi][nj][r] = 0.0f;

    // prologue: fill stages 0..2
#pragma unroll
    for (int kt = 0; kt < STAGES - 1; kt++) load_stage(ubase, kt, kt, m0, n0);

    // ldmatrix lane addressing (stage-relative)
    // A frag (x4): lanes 0-15 rows m0-15 chunk lo; lanes 16-31 same rows chunk hi
    const int a_row = wm + (lane & 15);
    const int a_chi = lane >> 4;  // 0/1 -> +16B (k+8)
    // B frag (x4): lanes 0-7 n0-7 lo; 8-15 n0-7 hi; 16-23 n8-15 lo; 24-31 n8-15 hi
    const int b_row = wn + ((lane >> 4) << 3) + (lane & 7);
    const int b_chi = (lane >> 3) & 1;

    for (int kt = 0; kt < KTILES; kt++) {
        CP_WAIT(2);
        __syncthreads();

        const uint32_t sA = ubase + (kt % STAGES) * STAGE_BYTES;
        const uint32_t sB = sA + A_STAGE_BYTES;

        {   // refill the stage consumed this iter with tile kt+3
            const int lt = kt + STAGES - 1;
            if (lt < KTILES) load_stage(ubase, lt % STAGES, lt, m0, n0);
            else CP_COMMIT();  // keep wait_group accounting uniform
        }

#pragma unroll
        for (int ks = 0; ks < BK / 16; ks++) {
            uint32_t a[4][4], b[2][4];
#pragma unroll
            for (int mi = 0; mi < 4; mi++) {
                int row = a_row + mi * 16;
                int ch = ks * 2 + a_chi;
                ldsm_x4(a[mi][0], a[mi][1], a[mi][2], a[mi][3],
                        sA + row * 128 + ((ch ^ (row & 7)) << 4));
            }
#pragma unroll
            for (int j = 0; j < 2; j++) {
                int row = b_row + j * 16;
                int ch = ks * 2 + b_chi;
                ldsm_x4(b[j][0], b[j][1], b[j][2], b[j][3],
                        sB + row * 128 + ((ch ^ (row & 7)) << 4));
            }
#pragma unroll
            for (int mi = 0; mi < 4; mi++)
#pragma unroll
                for (int j = 0; j < 2; j++) {
                    mma16816(acc[mi][2 * j],     a[mi], b[j][0], b[j][1]);
                    mma16816(acc[mi][2 * j + 1], a[mi], b[j][2], b[j][3]);
                }
        }
    }

    // Epilogue: direct gmem float2 stores, bias fused.
    // D frag: d0,d1 -> (row = lane>>2, col = 2*(lane&3)); d2,d3 -> row+8.
    const int er = lane >> 2;
    const int ec = (lane & 3) * 2;
#pragma unroll
    for (int mi = 0; mi < 4; mi++) {
        const size_t row = (size_t)(m0 + wm + mi * 16 + er);
#pragma unroll
        for (int nj = 0; nj < 4; nj++) {
            const int col = n0 + wn + nj * 8 + ec;
            const float2 bv = __ldg(reinterpret_cast<const float2*>(bias + col));
            float2 v0, v1;
            v0.x = acc[mi][nj][0] + bv.x;
            v0.y = acc[mi][nj][1] + bv.y;
            v1.x = acc[mi][nj][2] + bv.x;
            v1.y = acc[mi][nj][3] + bv.y;
            *reinterpret_cast<float2*>(out + row * Ndim + col) = v0;
            *reinterpret_cast<float2*>(out + (row + 8) * Ndim + col) = v1;
        }
    }
}

// ---------------- launch ----------------

extern "C" void kernel_launch(void* const* d_in, const int* in_sizes, int n_in,
                              void* d_out, int out_size) {
    const float* x = nullptr;
    const float* W = nullptr;
    const float* bias = nullptr;
    for (int i = 0; i < n_in; i++) {
        if (in_sizes[i] == Mdim * Kdim) x = (const float*)d_in[i];
        else if (in_sizes[i] == Kdim * Ndim) W = (const float*)d_in[i];
        else if (in_sizes[i] == Ndim) bias = (const float*)d_in[i];
    }
    float* out = (float*)d_out;

    cudaFuncSetAttribute(gemm_kernel,
                         cudaFuncAttributeMaxDynamicSharedMemorySize, DYN_SMEM);

    // x -> fp16 (K-major)
    conv_x_kernel<<<(int)((size_t)Mdim * Kdim / 4 / 256), 256>>>(x);
    // W -> W^T fp16 (K-major)
    conv_w_kernel<<<dim3(Ndim / 32, Kdim / 32), dim3(32, 8)>>>(W);
    // GEMM
    gemm_kernel<<<dim3(Ndim / BN, Mdim / BM), NTHREADS, DYN_SMEM>>>(bias, out);
}